// round 2
// baseline (speedup 1.0000x reference)
#include <cuda_runtime.h>

#define BB 4
#define NN 2048
#define MM 2049
#define GG 1024
#define CC 3

typedef unsigned long long u64;

// ---------------- scratch (device globals; no allocations allowed) ----------
__device__ int   g_nearest[BB*NN];
__device__ int   g_nmax[BB];
__device__ u64   g_bestg[BB*GG];   // packed (dist_bits<<32 | pred_idx), ~0 = not assigned
__device__ int   g_next[BB*NN];
__device__ int   g_cnt[BB*NN];
__device__ u64   g_keep[BB*NN];    // packed (dist_bits<<32 | row_idx)
__device__ float g_cd[BB], g_sem[BB], g_mf[BB], g_mb[BB];

// pos = position * 0.15 + bias, with NO fma contraction (match XLA's separate ops)
__device__ __forceinline__ float posx_of(float p){ return __fadd_rn(__fmul_rn(p,0.15f), -29.925f); }
__device__ __forceinline__ float posy_of(float p){ return __fadd_rn(__fmul_rn(p,0.15f), -14.925f); }

__device__ __forceinline__ float pdist(float ax,float ay,float bx,float by){
    float dx = __fsub_rn(ax,bx), dy = __fsub_rn(ay,by);
    float d2 = __fadd_rn(__fmul_rn(dx,dx), __fmul_rn(dy,dy));
    return sqrtf(d2);
}

// ---------------- init scratch --------------------------------------------
__global__ void k_init() {
    int i = blockIdx.x*blockDim.x + threadIdx.x;
    if (i < BB*NN) { g_cnt[i] = 0; g_keep[i] = ~0ULL; }
    if (i < BB*GG)   g_bestg[i] = ~0ULL;
    if (i < BB) { g_nmax[i]=0; g_cd[i]=0.f; g_sem[i]=0.f; g_mf[i]=0.f; g_mb[i]=0.f; }
}

// ---------------- zero the A block of the output (67 MB) -------------------
__global__ void k_zeroA(float* __restrict__ out) {
    long long t = (long long)blockIdx.x*blockDim.x + threadIdx.x;
    const long long E = (long long)BB*MM*MM;      // 16793604
    const long long n4 = (E-1)/4;                 // vector part, starts at out+4 (16B aligned)
    float4* v = (float4*)(out + 4);
    if (t < n4) v[t] = make_float4(0.f,0.f,0.f,0.f);
    if (t == 0) {
        out[3] = 0.f;                             // leading scalar
        for (long long k = 4 + 4*n4; k < 3 + E; ++k) out[k] = 0.f;  // tail scalars
    }
}

// ---------------- nearest gt per prediction (8 lanes per pred) -------------
__global__ void k_nearest(const float* __restrict__ positions,
                          const float* __restrict__ gt_pts,
                          const int*   __restrict__ gt_type,
                          const float* __restrict__ semantics,
                          float* __restrict__ sg_out)
{
    __shared__ float2 spt[GG];
    int b     = blockIdx.x >> 6;            // 64 blocks per batch (N/32 preds)
    int pred0 = (blockIdx.x & 63) * 32;
    int tid   = threadIdx.x;

    const float2* gp2 = (const float2*)(gt_pts + (size_t)b*GG*2);
    for (int g = tid; g < GG; g += 256) spt[g] = gp2[g];
    __syncthreads();

    int pred = pred0 + (tid >> 3);
    int part = tid & 7;

    float2 praw = ((const float2*)(positions))[b*NN + pred];
    float px = posx_of(praw.x), py = posy_of(praw.y);

    float bestd = 3.4e38f; int bestg = 0;
    int g0 = part * (GG/8);
    #pragma unroll 4
    for (int k = 0; k < GG/8; ++k) {
        int g = g0 + k;
        float d = pdist(px, py, spt[g].x, spt[g].y);
        if (d < bestd) { bestd = d; bestg = g; }   // strict <  -> first index wins
    }
    u64 key = ((u64)__float_as_uint(bestd) << 32) | (unsigned)bestg;
    #pragma unroll
    for (int o = 4; o; o >>= 1) {
        u64 other = __shfl_down_sync(0xffffffffu, key, o, 8);
        if (other < key) key = other;              // tie -> smaller g (low bits)
    }
    if (part == 0) {
        int gb  = (int)(key & 0xffffffffULL);
        float d = __uint_as_float((unsigned)(key >> 32));
        int bi  = b*NN + pred;
        g_nearest[bi] = gb;
        atomicMax(&g_nmax[b], gb);
        atomicAdd(&g_cd[b], d);
        atomicMin(&g_bestg[b*GG + gb], ((u64)__float_as_uint(d) << 32) | (unsigned)pred);
        int cls = gt_type[b*GG + gb];
        float* sg = sg_out + (size_t)b*CC*NN;
        sg[0*NN + pred] = (cls==0) ? 1.f : 0.f;
        sg[1*NN + pred] = (cls==1) ? 1.f : 0.f;
        sg[2*NN + pred] = (cls==2) ? 1.f : 0.f;
        atomicAdd(&g_sem[b], semantics[(size_t)b*CC*NN + (size_t)cls*NN + pred]);
    }
}

// ---------------- walk + column counts + keep (dedup argmin) ---------------
__global__ void k_walk(const int* __restrict__ gt_ins,
                       const float* __restrict__ positions)
{
    int i = blockIdx.x*blockDim.x + threadIdx.x;
    if (i >= BB*NN) return;
    int b = i / NN, ii = i % NN;
    const int* ins = gt_ins + b*GG;
    const u64* bg  = g_bestg + b*GG;
    int nmaxb = g_nmax[b];

    int idx = g_nearest[i];
    int steps = 0, res = -1;
    // literal transcription of the jax while_loop (incl. -1 wraparound + step cap)
    while (true) {
        bool is_end = (idx >= nmaxb);
        int  gnr    = is_end ? -1 : (idx + 1);
        int  gn     = gnr & (GG-1);                 // jnp.mod for GG power of 2
        u64  v      = bg[gn];
        bool ex     = (!is_end) && (v != ~0ULL);
        bool same   = (ins[idx & (GG-1)] == ins[gn]);
        bool matched= ex && same;
        res  = matched ? (int)(v & 0xffffffffULL) : -1;
        bool stop = matched || (!same) || (steps >= GG + 2);
        idx = gnr; steps++;
        if (stop) break;
    }
    g_next[i] = res;

    if (res >= 0) {
        atomicAdd(&g_cnt[b*NN + res], 1);
        float2 pi = ((const float2*)positions)[b*NN + ii];
        float2 pj = ((const float2*)positions)[b*NN + res];
        float d = pdist(posx_of(pi.x), posy_of(pi.y), posx_of(pj.x), posy_of(pj.y));
        atomicMin(&g_keep[b*NN + res], ((u64)__float_as_uint(d) << 32) | (unsigned)ii);
    }
}

// ---------------- row finalize: one 1 per row, loss_f ----------------------
__global__ void k_rows(const float* __restrict__ matches, float* __restrict__ A)
{
    int i = blockIdx.x*blockDim.x + threadIdx.x;   // exactly BB*NN threads
    int b = i / NN, ii = i % NN;
    int res = g_next[i];
    int tgt;
    if (res >= 0) {
        int cnt = g_cnt[b*NN + res];
        bool kept = (cnt <= 1) || ((int)(g_keep[b*NN + res] & 0xffffffffULL) == ii);
        tgt = kept ? res : (MM-1);
    } else {
        tgt = MM-1;
    }
    size_t base = (size_t)b*MM*MM + (size_t)ii*MM;
    A[base + tgt] = 1.0f;
    float v = matches[base + tgt];                 // match[ii, tgt_f[ii]]
    #pragma unroll
    for (int o = 16; o; o >>= 1) v += __shfl_xor_sync(0xffffffffu, v, o);
    if ((threadIdx.x & 31) == 0) atomicAdd(&g_mf[b], v);   // whole warp same b (N%256==0)
}

// ---------------- column finalize: bottom row, loss_b ----------------------
__global__ void k_cols(const float* __restrict__ matches, float* __restrict__ A)
{
    int i = blockIdx.x*blockDim.x + threadIdx.x;   // exactly BB*NN threads
    int b = i / NN, j = i % NN;
    int cnt = g_cnt[i];
    int tgtb;
    if (cnt == 0) {
        A[(size_t)b*MM*MM + (size_t)(MM-1)*MM + j] = 1.0f;
        tgtb = MM-1;
    } else {
        tgtb = (int)(g_keep[i] & 0xffffffffULL);   // cnt==1: the unique row; cnt>1: keep[j]
    }
    float v = matches[(size_t)b*MM*MM + (size_t)j*MM + tgtb];  // match[j, tgt_b[j]]
    #pragma unroll
    for (int o = 16; o; o >>= 1) v += __shfl_xor_sync(0xffffffffu, v, o);
    if ((threadIdx.x & 31) == 0) atomicAdd(&g_mb[b], v);
}

// ---------------- scalars --------------------------------------------------
__global__ void k_final(float* __restrict__ out)
{
    if (threadIdx.x == 0 && blockIdx.x == 0) {
        float cm = 0.f, ml = 0.f, sl = 0.f;
        const float invN = 1.0f / NN;
        for (int b = 0; b < BB; ++b) {
            cm += g_cd[b] * invN;
            sl += -g_sem[b] * invN;
            float lf = -g_mf[b] * invN;
            float lb = -g_mb[b] * invN;
            ml += 0.5f * (lf + lb);
        }
        const float invB = 1.0f / BB;
        out[0] = cm * invB;
        out[1] = ml * invB;
        out[2] = sl * invB;
    }
}

extern "C" void kernel_launch(void* const* d_in, const int* in_sizes, int n_in,
                              void* d_out, int out_size)
{
    const float* matches   = (const float*)d_in[0];
    const float* positions = (const float*)d_in[1];
    const float* semantics = (const float*)d_in[2];
    /* d_in[3] masks: unused by reference */
    const float* gt_pts    = (const float*)d_in[4];
    const int*   gt_ins    = (const int*)d_in[5];
    const int*   gt_type   = (const int*)d_in[6];

    float* out = (float*)d_out;
    float* A   = out + 3;
    float* sg  = out + 3 + (size_t)BB*MM*MM;

    k_init<<<(BB*NN + 255)/256, 256>>>();

    {
        long long E  = (long long)BB*MM*MM;
        long long n4 = (E-1)/4;
        int blocks = (int)((n4 + 255)/256);
        k_zeroA<<<blocks, 256>>>(out);
    }

    k_nearest<<<BB*NN/32, 256>>>(positions, gt_pts, gt_type, semantics, sg);
    k_walk<<<BB*NN/256, 256>>>(gt_ins, positions);
    k_rows<<<BB*NN/256, 256>>>(matches, A);
    k_cols<<<BB*NN/256, 256>>>(matches, A);
    k_final<<<1, 32>>>(out);
}

// round 3
// speedup vs baseline: 1.2323x; 1.2323x over previous
#include <cuda_runtime.h>

#define BB 4
#define NN 2048
#define MM 2049
#define GG 1024
#define CC 3

typedef unsigned long long u64;

// ---------------- scratch (device globals, zero-initialized at load) --------
// Self-cleaning invariant: every kernel sequence leaves these back at the
// all-zero state, so no init kernel is needed (empty sentinel == 0 via
// complemented key packing).
__device__ u64   g_bestg[BB*GG];   // ~((distbits<<32)|pred); 0 = unassigned
__device__ int   g_nmax[BB];
__device__ int   g_nearest[BB*NN]; // fully overwritten each run
__device__ int   g_nextg[BB*GG];   // fully overwritten each run
__device__ int   g_next[BB*NN];    // fully overwritten each run
__device__ int   g_cnt[BB*NN];
__device__ u64   g_keep[BB*NN];    // ~((distbits<<32)|row); 0 = empty
__device__ float g_cd[BB], g_sem[BB], g_mf[BB], g_mb[BB];

// pos = position * 0.15 + bias, with NO fma contraction (match XLA's separate ops)
__device__ __forceinline__ float posx_of(float p){ return __fadd_rn(__fmul_rn(p,0.15f), -29.925f); }
__device__ __forceinline__ float posy_of(float p){ return __fadd_rn(__fmul_rn(p,0.15f), -14.925f); }

__device__ __forceinline__ float pdist(float ax,float ay,float bx,float by){
    float dx = __fsub_rn(ax,bx), dy = __fsub_rn(ay,by);
    float d2 = __fadd_rn(__fmul_rn(dx,dx), __fmul_rn(dy,dy));
    return sqrtf(d2);
}

// ================= K1: zero out[0 .. 3+B*M*M)  ++  nearest-gt ==============
#define TOTF   (3 + BB*MM*MM)           // 16793607 floats to zero
#define ZVEC   (TOTF/4)                 // 4198401 float4
#define ZTAIL  (TOTF & 3)               // 3
#define NBLK   (BB*NN/32)               // 256 nearest blocks (32 preds each)
#define ZBLK   ((ZVEC + 255)/256)       // 16401 zero blocks

__global__ void k1_zero_nearest(const float* __restrict__ positions,
                                const float* __restrict__ gt_pts,
                                const int*   __restrict__ gt_type,
                                const float* __restrict__ semantics,
                                float* __restrict__ out,
                                float* __restrict__ sg_out)
{
    __shared__ float2 spt[GG];

    if (blockIdx.x >= NBLK) {            // -------- zeroing blocks ----------
        long long t = (long long)(blockIdx.x - NBLK)*256 + threadIdx.x;
        if (t < ZVEC) ((float4*)out)[t] = make_float4(0.f,0.f,0.f,0.f);
        if (t == 0) {
            #pragma unroll
            for (int k = 0; k < ZTAIL; ++k) out[4LL*ZVEC + k] = 0.f;
        }
        return;
    }

    // ---------------- nearest blocks (scheduled first = wave 1) ------------
    int b     = blockIdx.x >> 6;         // 64 blocks per batch
    int pred0 = (blockIdx.x & 63) * 32;
    int tid   = threadIdx.x;

    const float2* gp2 = (const float2*)(gt_pts + (size_t)b*GG*2);
    for (int g = tid; g < GG; g += 256) spt[g] = gp2[g];
    __syncthreads();

    int pred = pred0 + (tid >> 3);
    int part = tid & 7;

    float2 praw = ((const float2*)(positions))[b*NN + pred];
    float px = posx_of(praw.x), py = posy_of(praw.y);

    float bestd = 3.4e38f; int bestg = 0;
    int g0 = part * (GG/8);
    #pragma unroll 4
    for (int k = 0; k < GG/8; ++k) {
        int g = g0 + k;
        float d = pdist(px, py, spt[g].x, spt[g].y);
        if (d < bestd) { bestd = d; bestg = g; }      // strict <  -> first idx
    }
    u64 key = ((u64)__float_as_uint(bestd) << 32) | (unsigned)bestg;
    #pragma unroll
    for (int o = 4; o; o >>= 1) {
        u64 other = __shfl_down_sync(0xffffffffu, key, o, 8);
        if (other < key) key = other;                 // tie -> smaller g
    }
    if (part == 0) {
        int gb  = (int)(key & 0xffffffffULL);
        float d = __uint_as_float((unsigned)(key >> 32));
        int bi  = b*NN + pred;
        g_nearest[bi] = gb;
        atomicMax(&g_nmax[b], gb);
        atomicAdd(&g_cd[b], d);
        u64 pk = ((u64)__float_as_uint(d) << 32) | (unsigned)pred;
        atomicMax(&g_bestg[b*GG + gb], ~pk);          // min(key) == max(~key)
        int cls = gt_type[b*GG + gb];
        float* sg = sg_out + (size_t)b*CC*NN;
        sg[0*NN + pred] = (cls==0) ? 1.f : 0.f;
        sg[1*NN + pred] = (cls==1) ? 1.f : 0.f;
        sg[2*NN + pred] = (cls==2) ? 1.f : 0.f;
        atomicAdd(&g_sem[b], semantics[(size_t)b*CC*NN + (size_t)cls*NN + pred]);
    }
}

// ================= K2: walk once per gt index (dedup over preds) ===========
__global__ void k2_walkg(const int* __restrict__ gt_ins)
{
    int i = blockIdx.x*blockDim.x + threadIdx.x;      // BB*GG threads
    int b = i >> 10;
    const int* ins = gt_ins + b*GG;
    const u64* bg  = g_bestg + b*GG;
    int nmaxb = g_nmax[b];

    int idx = i & (GG-1);                             // start = this g
    int steps = 0, res = -1;
    while (true) {                                    // literal jax while_loop
        bool is_end = (idx >= nmaxb);
        int  gnr    = is_end ? -1 : (idx + 1);
        int  gn     = gnr & (GG-1);
        u64  v      = bg[gn];
        bool ex     = (!is_end) && (v != 0ULL);
        bool same   = (ins[idx & (GG-1)] == ins[gn]);
        bool matched= ex && same;
        res  = matched ? (int)((~v) & 0xffffffffULL) : -1;
        bool stop = matched || (!same) || (steps >= GG + 2);
        idx = gnr; steps++;
        if (stop) break;
    }
    g_nextg[i] = res;
}

// ================= K3: per-pred lookup + column counts + keep ==============
__global__ void k3_count(const float* __restrict__ positions)
{
    int i = blockIdx.x*blockDim.x + threadIdx.x;      // BB*NN threads
    int b = i >> 11, ii = i & (NN-1);
    int res = g_nextg[b*GG + g_nearest[i]];
    g_next[i] = res;
    if (res >= 0) {
        atomicAdd(&g_cnt[b*NN + res], 1);
        float2 pi = ((const float2*)positions)[i];
        float2 pj = ((const float2*)positions)[b*NN + res];
        float d = pdist(posx_of(pi.x), posy_of(pi.y), posx_of(pj.x), posy_of(pj.y));
        u64 pk = ((u64)__float_as_uint(d) << 32) | (unsigned)ii;
        atomicMax(&g_keep[b*NN + res], ~pk);
    }
    if (i < BB*GG) g_bestg[i] = 0ULL;                 // self-clean (done being read)
}

// ================= K4: rows (tgt_f, loss_f)  ++  cols (tgt_b, loss_b) ======
__global__ void k4_rowscols(const float* __restrict__ matches, float* __restrict__ A)
{
    int t = blockIdx.x*blockDim.x + threadIdx.x;      // 2*BB*NN threads
    float v;
    float* acc;
    int b;
    if (t < BB*NN) {                                  // ---- row side ----
        int i = t; b = i >> 11; int ii = i & (NN-1);
        int res = g_next[i];
        int tgt;
        if (res >= 0) {
            int cnt = g_cnt[b*NN + res];
            int keeprow = (int)((~g_keep[b*NN + res]) & 0xffffffffULL);
            tgt = (cnt <= 1 || keeprow == ii) ? res : (MM-1);
        } else tgt = MM-1;
        size_t base = (size_t)b*MM*MM + (size_t)ii*MM;
        A[base + tgt] = 1.0f;
        v = matches[base + tgt];
        acc = g_mf;
    } else {                                          // ---- col side ----
        int i = t - BB*NN; b = i >> 11; int j = i & (NN-1);
        int cnt = g_cnt[i];
        int tgtb;
        if (cnt == 0) {
            A[(size_t)b*MM*MM + (size_t)(MM-1)*MM + j] = 1.0f;
            tgtb = MM-1;
        } else {
            tgtb = (int)((~g_keep[i]) & 0xffffffffULL);
        }
        v = matches[(size_t)b*MM*MM + (size_t)j*MM + tgtb];
        acc = g_mb;
    }
    #pragma unroll
    for (int o = 16; o; o >>= 1) v += __shfl_xor_sync(0xffffffffu, v, o);
    if ((threadIdx.x & 31) == 0) atomicAdd(&acc[b], v);   // warp-uniform b
}

// ================= K5: scalars + scratch reset =============================
__global__ void k5_final(float* __restrict__ out)
{
    int i = blockIdx.x*blockDim.x + threadIdx.x;      // BB*NN threads
    g_cnt[i] = 0;                                     // self-clean (read in K4)
    g_keep[i] = 0ULL;
    if (i < BB) g_nmax[i] = 0;
    if (i == 0) {
        float cm = 0.f, ml = 0.f, sl = 0.f;
        const float invN = 1.0f / NN;
        for (int b = 0; b < BB; ++b) {
            cm += g_cd[b] * invN;
            sl += -g_sem[b] * invN;
            float lf = -g_mf[b] * invN;
            float lb = -g_mb[b] * invN;
            ml += 0.5f * (lf + lb);
            g_cd[b]=0.f; g_sem[b]=0.f; g_mf[b]=0.f; g_mb[b]=0.f;
        }
        const float invB = 1.0f / BB;
        out[0] = cm * invB;
        out[1] = ml * invB;
        out[2] = sl * invB;
    }
}

extern "C" void kernel_launch(void* const* d_in, const int* in_sizes, int n_in,
                              void* d_out, int out_size)
{
    const float* matches   = (const float*)d_in[0];
    const float* positions = (const float*)d_in[1];
    const float* semantics = (const float*)d_in[2];
    /* d_in[3] masks: unused by reference */
    const float* gt_pts    = (const float*)d_in[4];
    const int*   gt_ins    = (const int*)d_in[5];
    const int*   gt_type   = (const int*)d_in[6];

    float* out = (float*)d_out;
    float* A   = out + 3;
    float* sg  = out + 3 + (size_t)BB*MM*MM;

    k1_zero_nearest<<<NBLK + ZBLK, 256>>>(positions, gt_pts, gt_type, semantics, out, sg);
    k2_walkg<<<BB*GG/256, 256>>>(gt_ins);
    k3_count<<<BB*NN/256, 256>>>(positions);
    k4_rowscols<<<2*BB*NN/256, 256>>>(matches, A);
    k5_final<<<BB*NN/256, 256>>>(out);
}